// round 1
// baseline (speedup 1.0000x reference)
#include <cuda_runtime.h>
#include <math.h>

#define N_NODES 100000
#define IN_DIM 64
#define HALF 32

// ---------------- scratch (device globals: allocation-free) ----------------
__device__ float4 g_aggP[N_NODES * 16];   // 100k x 64 floats
__device__ float4 g_aggN[N_NODES * 16];
__device__ float4 g_z[N_NODES * 16];      // tanh output of layer 1
__device__ float  g_cntP[N_NODES];
__device__ float  g_cntN[N_NODES];

// ---------------- zero kernels ----------------
__global__ void zero_layer1() {
    int i = blockIdx.x * blockDim.x + threadIdx.x;
    float4 z4 = make_float4(0.f, 0.f, 0.f, 0.f);
    if (i < N_NODES * 16) { g_aggP[i] = z4; g_aggN[i] = z4; }
    if (i < N_NODES)      { g_cntP[i] = 0.f; g_cntN[i] = 0.f; }
}
__global__ void zero_layer2() {
    int i = blockIdx.x * blockDim.x + threadIdx.x;
    float4 z4 = make_float4(0.f, 0.f, 0.f, 0.f);
    if (i < N_NODES * 16) { g_aggP[i] = z4; g_aggN[i] = z4; }
}

// ---------------- edge aggregation ----------------
// featSel: 0 = external x (xfeat), 1 = g_z
// outSel:  0 = g_aggP, 1 = g_aggN
// doCnt:   1 = also count edges per dst (layer 1 only)
__global__ void __launch_bounds__(256)
agg_kernel(const float4* __restrict__ xfeat,
           const int* __restrict__ src, const int* __restrict__ dst,
           int nEdges, int featSel, int outSel, int doCnt)
{
    int t = blockIdx.x * blockDim.x + threadIdx.x;
    if (t >= nEdges * 16) return;
    int e = t >> 4;
    int c = t & 15;
    int s = __ldg(src + e);
    int d = __ldg(dst + e);
    const float4* feat = featSel ? (const float4*)g_z : xfeat;
    float4* out = outSel ? g_aggN : g_aggP;
    float4 v = __ldg(feat + s * 16 + c);
    float4* p = out + d * 16 + c;
    asm volatile("red.global.add.v4.f32 [%0], {%1,%2,%3,%4};"
                 :: "l"(p), "f"(v.x), "f"(v.y), "f"(v.z), "f"(v.w) : "memory");
    if (doCnt && c == 0) {
        float* cnt = outSel ? g_cntN : g_cntP;
        atomicAdd(cnt + d, 1.0f);
    }
}

// ---------------- layer 1: z = tanh([aggP/c,x]@w1b+b1b  ||  [aggN/c,x]@w1u+b1u) ----------------
__global__ void __launch_bounds__(256)
linear1_kernel(const float* __restrict__ x,
               const float* __restrict__ w1b, const float* __restrict__ b1b,
               const float* __restrict__ w1u, const float* __restrict__ b1u)
{
    __shared__ float sW[2][128 * 32];   // [0]=w1b, [1]=w1u, layout k*32+j (row-major as given)
    __shared__ float sB[64];
    __shared__ float sIn[4][3][64];     // per node group: aggP/c, aggN/c, x
    int tid = threadIdx.x;
    for (int i = tid; i < 128 * 32; i += 256) { sW[0][i] = w1b[i]; sW[1][i] = w1u[i]; }
    if (tid < 32) { sB[tid] = b1b[tid]; sB[32 + tid] = b1u[tid]; }
    __syncthreads();

    int g = tid >> 6;          // node within group of 4
    int j = tid & 63;          // output index 0..63
    const float* aggP = (const float*)g_aggP;
    const float* aggN = (const float*)g_aggN;
    float* zout = (float*)g_z;

    for (int n0 = blockIdx.x * 4; n0 < N_NODES; n0 += gridDim.x * 4) {
        int n = n0 + g;
        if (n < N_NODES) {
            float invP = 1.0f / fmaxf(g_cntP[n], 1.0f);
            float invN = 1.0f / fmaxf(g_cntN[n], 1.0f);
            sIn[g][0][j] = aggP[n * 64 + j] * invP;
            sIn[g][1][j] = aggN[n * 64 + j] * invN;
            sIn[g][2][j] = x[n * 64 + j];
        }
        __syncthreads();
        if (n < N_NODES) {
            int half = j >> 5;          // 0 -> b branch, 1 -> u branch
            int jj = j & 31;
            const float* W   = sW[half];
            const float* inA = sIn[g][half];   // aggP for b, aggN for u
            const float* inX = sIn[g][2];
            float acc = sB[j];
            #pragma unroll
            for (int k = 0; k < 64; k++) acc = fmaf(inA[k], W[k * 32 + jj], acc);
            #pragma unroll
            for (int k = 0; k < 64; k++) acc = fmaf(inX[k], W[(64 + k) * 32 + jj], acc);
            zout[n * 64 + j] = tanhf(acc);
        }
        __syncthreads();
    }
}

// ---------------- layer 2 ----------------
// inB[96] = [aggP[0:32]/cP, aggN[32:64]/cN, z[0:32]]   -> w2b,b2b
// inU[96] = [aggP[32:64]/cP, aggN[0:32]/cN, z[32:64]]  -> w2u,b2u
__global__ void __launch_bounds__(256)
linear2_kernel(const float* __restrict__ w2b, const float* __restrict__ b2b,
               const float* __restrict__ w2u, const float* __restrict__ b2u,
               float* __restrict__ out)
{
    __shared__ float sW[2][96 * 32];
    __shared__ float sB[64];
    __shared__ float sIn[4][2][96];
    int tid = threadIdx.x;
    for (int i = tid; i < 96 * 32; i += 256) { sW[0][i] = w2b[i]; sW[1][i] = w2u[i]; }
    if (tid < 32) { sB[tid] = b2b[tid]; sB[32 + tid] = b2u[tid]; }
    __syncthreads();

    int g = tid >> 6;
    int j = tid & 63;
    const float* aggP = (const float*)g_aggP;
    const float* aggN = (const float*)g_aggN;
    const float* z = (const float*)g_z;

    for (int n0 = blockIdx.x * 4; n0 < N_NODES; n0 += gridDim.x * 4) {
        int n = n0 + g;
        if (n < N_NODES) {
            float invP = 1.0f / fmaxf(g_cntP[n], 1.0f);
            float invN = 1.0f / fmaxf(g_cntN[n], 1.0f);
            for (int idx = j; idx < 192; idx += 64) {
                int vec = idx / 96;
                int k = idx - vec * 96;
                float v;
                if (vec == 0) {
                    if (k < 32)      v = aggP[n * 64 + k] * invP;
                    else if (k < 64) v = aggN[n * 64 + k] * invN;
                    else             v = z[n * 64 + (k - 64)];
                } else {
                    if (k < 32)      v = aggP[n * 64 + 32 + k] * invP;
                    else if (k < 64) v = aggN[n * 64 + (k - 32)] * invN;
                    else             v = z[n * 64 + 32 + (k - 64)];
                }
                sIn[g][vec][k] = v;
            }
        }
        __syncthreads();
        if (n < N_NODES) {
            int half = j >> 5;
            int jj = j & 31;
            const float* W  = sW[half];
            const float* in = sIn[g][half];
            float acc = sB[j];
            #pragma unroll
            for (int k = 0; k < 96; k++) acc = fmaf(in[k], W[k * 32 + jj], acc);
            out[n * 64 + j] = tanhf(acc);
        }
        __syncthreads();
    }
}

// ---------------- launch ----------------
extern "C" void kernel_launch(void* const* d_in, const int* in_sizes, int n_in,
                              void* d_out, int out_size)
{
    const float* x    = (const float*)d_in[0];
    const int* posEI  = (const int*)d_in[1];
    const int* negEI  = (const int*)d_in[2];
    const float* w1b  = (const float*)d_in[3];
    const float* b1b  = (const float*)d_in[4];
    const float* w1u  = (const float*)d_in[5];
    const float* b1u  = (const float*)d_in[6];
    const float* w2b  = (const float*)d_in[7];
    const float* b2b  = (const float*)d_in[8];
    const float* w2u  = (const float*)d_in[9];
    const float* b2u  = (const float*)d_in[10];
    float* out = (float*)d_out;

    int E = in_sizes[1] / 2;             // 1,600,000
    const int* posSrc = posEI;
    const int* posDst = posEI + E;
    const int* negSrc = negEI;
    const int* negDst = negEI + E;

    int zeroGrid = (N_NODES * 16 + 255) / 256;
    int aggGrid  = (E * 16 + 255) / 256;

    zero_layer1<<<zeroGrid, 256>>>();
    agg_kernel<<<aggGrid, 256>>>((const float4*)x, posSrc, posDst, E, 0, 0, 1);
    agg_kernel<<<aggGrid, 256>>>((const float4*)x, negSrc, negDst, E, 0, 1, 1);
    linear1_kernel<<<1024, 256>>>(x, w1b, b1b, w1u, b1u);
    zero_layer2<<<zeroGrid, 256>>>();
    agg_kernel<<<aggGrid, 256>>>((const float4*)x, posSrc, posDst, E, 1, 0, 0);
    agg_kernel<<<aggGrid, 256>>>((const float4*)x, negSrc, negDst, E, 1, 1, 0);
    linear2_kernel<<<1024, 256>>>(w2b, b2b, w2u, b2u, out);
}

// round 2
// speedup vs baseline: 1.2972x; 1.2972x over previous
#include <cuda_runtime.h>
#include <math.h>

#define N_NODES 100000
#define IN_DIM 64
#define HALF 32

// ---------------- scratch (device globals: allocation-free) ----------------
__device__ float4 g_aggP[N_NODES * 16];   // 100k x 64 floats
__device__ float4 g_aggN[N_NODES * 16];
__device__ float4 g_z[N_NODES * 16];      // tanh output of layer 1
__device__ float  g_cntP[N_NODES];
__device__ float  g_cntN[N_NODES];

// ---------------- zero kernels ----------------
__global__ void zero_layer1() {
    int i = blockIdx.x * blockDim.x + threadIdx.x;
    float4 z4 = make_float4(0.f, 0.f, 0.f, 0.f);
    if (i < N_NODES * 16) { g_aggP[i] = z4; g_aggN[i] = z4; }
    if (i < N_NODES)      { g_cntP[i] = 0.f; g_cntN[i] = 0.f; }
}
__global__ void zero_layer2() {
    int i = blockIdx.x * blockDim.x + threadIdx.x;
    float4 z4 = make_float4(0.f, 0.f, 0.f, 0.f);
    if (i < N_NODES * 16) { g_aggP[i] = z4; g_aggN[i] = z4; }
}

// ---------------- edge aggregation ----------------
__global__ void __launch_bounds__(256)
agg_kernel(const float4* __restrict__ xfeat,
           const int* __restrict__ src, const int* __restrict__ dst,
           int nEdges, int featSel, int outSel, int doCnt)
{
    int t = blockIdx.x * blockDim.x + threadIdx.x;
    if (t >= nEdges * 16) return;
    int e = t >> 4;
    int c = t & 15;
    int s = __ldg(src + e);
    int d = __ldg(dst + e);
    const float4* feat = featSel ? (const float4*)g_z : xfeat;
    float4* out = outSel ? g_aggN : g_aggP;
    float4 v = __ldg(feat + s * 16 + c);
    float4* p = out + d * 16 + c;
    asm volatile("red.global.add.v4.f32 [%0], {%1,%2,%3,%4};"
                 :: "l"(p), "f"(v.x), "f"(v.y), "f"(v.z), "f"(v.w) : "memory");
    if (doCnt && c == 0) {
        float* cnt = outSel ? g_cntN : g_cntP;
        atomicAdd(cnt + d, 1.0f);
    }
}

// ---------------- layer 1 (register-tiled GEMM) ----------------
// branch0 (j 0..31):  tanh( [aggP*invP, x] @ w1b + b1b )
// branch1 (j 32..63): tanh( [aggN*invN, x] @ w1u + b1u )
// thread tile: 4 nodes x 4 outputs; outputs j = branch*32 + jb + 8*o
#define RS1 132
__global__ void __launch_bounds__(256)
linear1_v2(const float* __restrict__ x,
           const float* __restrict__ w1b, const float* __restrict__ b1b,
           const float* __restrict__ w1u, const float* __restrict__ b1u)
{
    __shared__ float sW[2][32][RS1];   // transposed: sW[branch][j][k]
    __shared__ float sB[64];
    int tid = threadIdx.x;
    for (int i = tid; i < 128 * 32; i += 256) {
        int k = i >> 5, j = i & 31;
        sW[0][j][k] = w1b[i];
        sW[1][j][k] = w1u[i];
    }
    if (tid < 32) { sB[tid] = b1b[tid]; sB[tid + 32] = b1u[tid]; }
    __syncthreads();

    int jg = tid & 15, ng = tid >> 4;
    int branch = jg >> 3, jb = jg & 7;
    const float* agg = branch ? (const float*)g_aggN : (const float*)g_aggP;
    const float* cnt = branch ? g_cntN : g_cntP;
    float* zout = (float*)g_z;

    int nbase = blockIdx.x * 64 + ng * 4;
    int nidx[4];
    float inv[4];
    #pragma unroll
    for (int ni = 0; ni < 4; ni++) {
        int n = nbase + ni; if (n > N_NODES - 1) n = N_NODES - 1;
        nidx[ni] = n;
        inv[ni] = 1.0f / fmaxf(cnt[n], 1.0f);
    }

    float acc[4][4], tmp[4][4];
    #pragma unroll
    for (int ni = 0; ni < 4; ni++)
        #pragma unroll
        for (int o = 0; o < 4; o++) {
            acc[ni][o] = sB[branch * 32 + jb + 8 * o];
            tmp[ni][o] = 0.f;
        }

    // region A: aggregated features (k = 0..63) -> tmp (scaled at the end)
    #pragma unroll 4
    for (int ch = 0; ch < 16; ch++) {
        float4 v[4], w[4];
        #pragma unroll
        for (int ni = 0; ni < 4; ni++)
            v[ni] = *(const float4*)(agg + nidx[ni] * 64 + ch * 4);
        #pragma unroll
        for (int o = 0; o < 4; o++)
            w[o] = *(const float4*)&sW[branch][jb + 8 * o][ch * 4];
        #pragma unroll
        for (int ni = 0; ni < 4; ni++)
            #pragma unroll
            for (int o = 0; o < 4; o++) {
                tmp[ni][o] = fmaf(v[ni].x, w[o].x, tmp[ni][o]);
                tmp[ni][o] = fmaf(v[ni].y, w[o].y, tmp[ni][o]);
                tmp[ni][o] = fmaf(v[ni].z, w[o].z, tmp[ni][o]);
                tmp[ni][o] = fmaf(v[ni].w, w[o].w, tmp[ni][o]);
            }
    }
    // region B: self features x (k = 64..127) -> acc
    #pragma unroll 4
    for (int ch = 0; ch < 16; ch++) {
        float4 v[4], w[4];
        #pragma unroll
        for (int ni = 0; ni < 4; ni++)
            v[ni] = *(const float4*)(x + nidx[ni] * 64 + ch * 4);
        #pragma unroll
        for (int o = 0; o < 4; o++)
            w[o] = *(const float4*)&sW[branch][jb + 8 * o][64 + ch * 4];
        #pragma unroll
        for (int ni = 0; ni < 4; ni++)
            #pragma unroll
            for (int o = 0; o < 4; o++) {
                acc[ni][o] = fmaf(v[ni].x, w[o].x, acc[ni][o]);
                acc[ni][o] = fmaf(v[ni].y, w[o].y, acc[ni][o]);
                acc[ni][o] = fmaf(v[ni].z, w[o].z, acc[ni][o]);
                acc[ni][o] = fmaf(v[ni].w, w[o].w, acc[ni][o]);
            }
    }

    #pragma unroll
    for (int ni = 0; ni < 4; ni++) {
        int n = nbase + ni;
        if (n < N_NODES) {
            #pragma unroll
            for (int o = 0; o < 4; o++) {
                float r = tanhf(acc[ni][o] + tmp[ni][o] * inv[ni]);
                zout[n * 64 + branch * 32 + jb + 8 * o] = r;
            }
        }
    }
}

// ---------------- layer 2 (register-tiled GEMM) ----------------
// branch0: in = [aggP[0:32]*invP,  aggN[32:64]*invN, z[0:32] ] @ w2b + b2b
// branch1: in = [aggP[32:64]*invP, aggN[0:32]*invN,  z[32:64]] @ w2u + b2u
#define RS2 100
__global__ void __launch_bounds__(256)
linear2_v2(const float* __restrict__ w2b, const float* __restrict__ b2b,
           const float* __restrict__ w2u, const float* __restrict__ b2u,
           float* __restrict__ out)
{
    __shared__ float sW[2][32][RS2];
    __shared__ float sB[64];
    int tid = threadIdx.x;
    for (int i = tid; i < 96 * 32; i += 256) {
        int k = i >> 5, j = i & 31;
        sW[0][j][k] = w2b[i];
        sW[1][j][k] = w2u[i];
    }
    if (tid < 32) { sB[tid] = b2b[tid]; sB[tid + 32] = b2u[tid]; }
    __syncthreads();

    int jg = tid & 15, ng = tid >> 4;
    int branch = jg >> 3, jb = jg & 7;
    const float* aggP = (const float*)g_aggP;
    const float* aggN = (const float*)g_aggN;
    const float* z = (const float*)g_z;

    int offA = branch * 32;          // aggP column offset
    int offB = (1 - branch) * 32;    // aggN column offset
    int offC = branch * 32;          // z column offset

    int nbase = blockIdx.x * 64 + ng * 4;
    int nidx[4];
    float invP[4], invN[4];
    #pragma unroll
    for (int ni = 0; ni < 4; ni++) {
        int n = nbase + ni; if (n > N_NODES - 1) n = N_NODES - 1;
        nidx[ni] = n;
        invP[ni] = 1.0f / fmaxf(g_cntP[n], 1.0f);
        invN[ni] = 1.0f / fmaxf(g_cntN[n], 1.0f);
    }

    float acc[4][4], tmp[4][4];
    #pragma unroll
    for (int ni = 0; ni < 4; ni++)
        #pragma unroll
        for (int o = 0; o < 4; o++) {
            acc[ni][o] = sB[branch * 32 + jb + 8 * o];
            tmp[ni][o] = 0.f;
        }

    // region A: aggP slice (k = 0..31) -> tmp, fold with invP
    #pragma unroll
    for (int ch = 0; ch < 8; ch++) {
        float4 v[4], w[4];
        #pragma unroll
        for (int ni = 0; ni < 4; ni++)
            v[ni] = *(const float4*)(aggP + nidx[ni] * 64 + offA + ch * 4);
        #pragma unroll
        for (int o = 0; o < 4; o++)
            w[o] = *(const float4*)&sW[branch][jb + 8 * o][ch * 4];
        #pragma unroll
        for (int ni = 0; ni < 4; ni++)
            #pragma unroll
            for (int o = 0; o < 4; o++) {
                tmp[ni][o] = fmaf(v[ni].x, w[o].x, tmp[ni][o]);
                tmp[ni][o] = fmaf(v[ni].y, w[o].y, tmp[ni][o]);
                tmp[ni][o] = fmaf(v[ni].z, w[o].z, tmp[ni][o]);
                tmp[ni][o] = fmaf(v[ni].w, w[o].w, tmp[ni][o]);
            }
    }
    #pragma unroll
    for (int ni = 0; ni < 4; ni++)
        #pragma unroll
        for (int o = 0; o < 4; o++) {
            acc[ni][o] = fmaf(tmp[ni][o], invP[ni], acc[ni][o]);
            tmp[ni][o] = 0.f;
        }

    // region B: aggN slice (k = 32..63) -> tmp, fold with invN
    #pragma unroll
    for (int ch = 0; ch < 8; ch++) {
        float4 v[4], w[4];
        #pragma unroll
        for (int ni = 0; ni < 4; ni++)
            v[ni] = *(const float4*)(aggN + nidx[ni] * 64 + offB + ch * 4);
        #pragma unroll
        for (int o = 0; o < 4; o++)
            w[o] = *(const float4*)&sW[branch][jb + 8 * o][32 + ch * 4];
        #pragma unroll
        for (int ni = 0; ni < 4; ni++)
            #pragma unroll
            for (int o = 0; o < 4; o++) {
                tmp[ni][o] = fmaf(v[ni].x, w[o].x, tmp[ni][o]);
                tmp[ni][o] = fmaf(v[ni].y, w[o].y, tmp[ni][o]);
                tmp[ni][o] = fmaf(v[ni].z, w[o].z, tmp[ni][o]);
                tmp[ni][o] = fmaf(v[ni].w, w[o].w, tmp[ni][o]);
            }
    }
    #pragma unroll
    for (int ni = 0; ni < 4; ni++)
        #pragma unroll
        for (int o = 0; o < 4; o++)
            acc[ni][o] = fmaf(tmp[ni][o], invN[ni], acc[ni][o]);

    // region C: z slice (k = 64..95) -> acc directly
    #pragma unroll
    for (int ch = 0; ch < 8; ch++) {
        float4 v[4], w[4];
        #pragma unroll
        for (int ni = 0; ni < 4; ni++)
            v[ni] = *(const float4*)(z + nidx[ni] * 64 + offC + ch * 4);
        #pragma unroll
        for (int o = 0; o < 4; o++)
            w[o] = *(const float4*)&sW[branch][jb + 8 * o][64 + ch * 4];
        #pragma unroll
        for (int ni = 0; ni < 4; ni++)
            #pragma unroll
            for (int o = 0; o < 4; o++) {
                acc[ni][o] = fmaf(v[ni].x, w[o].x, acc[ni][o]);
                acc[ni][o] = fmaf(v[ni].y, w[o].y, acc[ni][o]);
                acc[ni][o] = fmaf(v[ni].z, w[o].z, acc[ni][o]);
                acc[ni][o] = fmaf(v[ni].w, w[o].w, acc[ni][o]);
            }
    }

    #pragma unroll
    for (int ni = 0; ni < 4; ni++) {
        int n = nbase + ni;
        if (n < N_NODES) {
            #pragma unroll
            for (int o = 0; o < 4; o++)
                out[n * 64 + branch * 32 + jb + 8 * o] = tanhf(acc[ni][o]);
        }
    }
}

// ---------------- launch ----------------
extern "C" void kernel_launch(void* const* d_in, const int* in_sizes, int n_in,
                              void* d_out, int out_size)
{
    const float* x    = (const float*)d_in[0];
    const int* posEI  = (const int*)d_in[1];
    const int* negEI  = (const int*)d_in[2];
    const float* w1b  = (const float*)d_in[3];
    const float* b1b  = (const float*)d_in[4];
    const float* w1u  = (const float*)d_in[5];
    const float* b1u  = (const float*)d_in[6];
    const float* w2b  = (const float*)d_in[7];
    const float* b2b  = (const float*)d_in[8];
    const float* w2u  = (const float*)d_in[9];
    const float* b2u  = (const float*)d_in[10];
    float* out = (float*)d_out;

    int E = in_sizes[1] / 2;             // 1,600,000
    const int* posSrc = posEI;
    const int* posDst = posEI + E;
    const int* negSrc = negEI;
    const int* negDst = negEI + E;

    int zeroGrid = (N_NODES * 16 + 255) / 256;
    int aggGrid  = (E * 16 + 255) / 256;
    int linGrid  = (N_NODES + 63) / 64;   // 1563

    zero_layer1<<<zeroGrid, 256>>>();
    agg_kernel<<<aggGrid, 256>>>((const float4*)x, posSrc, posDst, E, 0, 0, 1);
    agg_kernel<<<aggGrid, 256>>>((const float4*)x, negSrc, negDst, E, 0, 1, 1);
    linear1_v2<<<linGrid, 256>>>(x, w1b, b1b, w1u, b1u);
    zero_layer2<<<zeroGrid, 256>>>();
    agg_kernel<<<aggGrid, 256>>>((const float4*)x, posSrc, posDst, E, 1, 0, 0);
    agg_kernel<<<aggGrid, 256>>>((const float4*)x, negSrc, negDst, E, 1, 1, 0);
    linear2_v2<<<linGrid, 256>>>(w2b, b2b, w2u, b2u, out);
}